// round 9
// baseline (speedup 1.0000x reference)
#include <cuda_runtime.h>
#include <cuda_bf16.h>
#include <cstdint>
#include <math.h>

// ---------------- problem constants ----------------
#define NB   16384
#define ZLD  513
#define XK   1024
#define HD   1024
#define LD   256
#define OUTC 513

// ---------------- scratch ----------------
__device__ __nv_bfloat16 g_Xh [NB * XK];
__device__ __nv_bfloat16 g_Xl [NB * XK];
__device__ __nv_bfloat16 g_H1h[NB * HD];
__device__ __nv_bfloat16 g_H1l[NB * HD];
__device__ __nv_bfloat16 g_H2h[NB * HD];
__device__ __nv_bfloat16 g_H2l[NB * HD];
__device__ float         g_P1 [NB * LD];
__device__ float         g_P2 [NB * LD];
// transposed + split weights: Wt[n*K+k] = W[k*N+n]
__device__ __nv_bfloat16 g_Wh1h[HD * 512], g_Wh1l[HD * 512];
__device__ __nv_bfloat16 g_Wc1h[HD * XK],  g_Wc1l[HD * XK];
__device__ __nv_bfloat16 g_Wh2h[LD * HD],  g_Wh2l[LD * HD];
__device__ __nv_bfloat16 g_Wc2h[LD * HD],  g_Wc2l[LD * HD];

// ---------------- helpers ----------------
__device__ __forceinline__ uint32_t smem_u32(const void* p) {
    uint32_t a;
    asm("{ .reg .u64 t; cvta.to.shared.u64 t, %1; cvt.u32.u64 %0, t; }" : "=r"(a) : "l"(p));
    return a;
}
__device__ __forceinline__ void ldsm4(uint32_t (&r)[4], uint32_t addr) {
    asm volatile("ldmatrix.sync.aligned.m8n8.x4.shared.b16 {%0,%1,%2,%3}, [%4];"
        : "=r"(r[0]), "=r"(r[1]), "=r"(r[2]), "=r"(r[3]) : "r"(addr));
}
__device__ __forceinline__ void mma16816(float (&d)[4], const uint32_t (&a)[4],
                                         uint32_t b0, uint32_t b1) {
    asm volatile("mma.sync.aligned.m16n8k16.row.col.f32.bf16.bf16.f32 "
        "{%0,%1,%2,%3}, {%4,%5,%6,%7}, {%8,%9}, {%0,%1,%2,%3};"
        : "+f"(d[0]), "+f"(d[1]), "+f"(d[2]), "+f"(d[3])
        : "r"(a[0]), "r"(a[1]), "r"(a[2]), "r"(a[3]), "r"(b0), "r"(b1));
}
__device__ __forceinline__ void cpasync16(uint32_t saddr, const void* g) {
    asm volatile("cp.async.cg.shared.global [%0], [%1], 16;" :: "r"(saddr), "l"(g));
}
__device__ __forceinline__ void cp_commit() { asm volatile("cp.async.commit_group;"); }
__device__ __forceinline__ void cp_wait1()  { asm volatile("cp.async.wait_group 1;"  ::: "memory"); }

__device__ __forceinline__ void split_bf16(float v, __nv_bfloat16& hi, __nv_bfloat16& lo) {
    hi = __float2bfloat16(v);
    lo = __float2bfloat16(v - __bfloat162float(hi));
}

// ---------------------------------------------------------------------------
// K0: X = [ z[:, :512] , ctx[:, i, :] ]  split to bf16 hi/lo
// ---------------------------------------------------------------------------
__global__ void prep_kernel(const float* __restrict__ z,
                            const float* __restrict__ ctx,
                            const float* __restrict__ ts,
                            const float* __restrict__ tp)
{
    int idx = blockIdx.x * blockDim.x + threadIdx.x;
    float t = tp[0];
    int i = 0;
    #pragma unroll
    for (int j = 0; j < 16; ++j) i += (ts[j] <= t) ? 1 : 0;
    if (i > 15) i = 15;
    int row = idx >> 10, c = idx & 1023;
    float v = (c < 512) ? z[(long)row * ZLD + c]
                        : ctx[((long)row * 16 + i) * 512 + (c - 512)];
    __nv_bfloat16 hi, lo; split_bf16(v, hi, lo);
    g_Xh[idx] = hi; g_Xl[idx] = lo;
}

// ---------------------------------------------------------------------------
// All 4 weight transposes + bf16 splits in ONE launch (job = blockIdx.z)
// ---------------------------------------------------------------------------
__global__ void wsplit_all(const float* __restrict__ Wh1, const float* __restrict__ Wc1,
                           const float* __restrict__ Wh2, const float* __restrict__ Wc2,
                           __nv_bfloat16* Th1, __nv_bfloat16* Tl1,
                           __nv_bfloat16* Tc1h, __nv_bfloat16* Tc1l,
                           __nv_bfloat16* Th2, __nv_bfloat16* Tl2,
                           __nv_bfloat16* Tc2h, __nv_bfloat16* Tc2l)
{
    const float* W; int K, N; __nv_bfloat16 *Th, *Tl;
    switch (blockIdx.z) {
        case 0: W = Wh1; K = 512;  N = HD; Th = Th1;  Tl = Tl1;  break;
        case 1: W = Wc1; K = XK;   N = HD; Th = Tc1h; Tl = Tc1l; break;
        case 2: W = Wh2; K = HD;   N = LD; Th = Th2;  Tl = Tl2;  break;
        default:W = Wc2; K = HD;   N = LD; Th = Tc2h; Tl = Tc2l; break;
    }
    if ((int)(blockIdx.x * 32) >= N || (int)(blockIdx.y * 32) >= K) return;

    __shared__ float s[32][33];
    int k = blockIdx.y * 32 + threadIdx.y;
    int n = blockIdx.x * 32 + threadIdx.x;
    s[threadIdx.y][threadIdx.x] = W[(long)k * N + n];
    __syncthreads();
    int nn = blockIdx.x * 32 + threadIdx.y;
    int kk = blockIdx.y * 32 + threadIdx.x;
    float v = s[threadIdx.x][threadIdx.y];
    __nv_bfloat16 hi, lo; split_bf16(v, hi, lo);
    Th[(long)nn * K + kk] = hi;
    Tl[(long)nn * K + kk] = lo;
}

// ---------------------------------------------------------------------------
// mma.sync bf16 GEMM (3-term hi/lo split), BATCHED over blockIdx.z (2 jobs).
// CTA tile 128x64, BK=32, 256 thr / 8 warps, warp tile 32x32 (4m x 2n grid).
// acc = 32 regs -> __launch_bounds__(256,3): 3 CTAs/SM = 24 warps.
// 3-stage cp.async pipeline (24KB/stage, 72KB total), one barrier per chunk.
// Stage layout: A_h 8K | A_l 8K | B_h 4K | B_l 4K   (rows 64B, XOR swizzle)
// ---------------------------------------------------------------------------
#define BK      32
#define AH_OFF  0u
#define AL_OFF  8192u
#define BH_OFF  16384u
#define BL_OFF  20480u
#define STAGE   24576
#define NSTAGE  3

template<int ACT>
__global__ __launch_bounds__(256, 3)
void mma_gemm2(const __nv_bfloat16* __restrict__ Ah0, const __nv_bfloat16* __restrict__ Al0,
               const __nv_bfloat16* __restrict__ Bh0, const __nv_bfloat16* __restrict__ Bl0,
               const float* __restrict__ bias0,
               __nv_bfloat16* Ch0, __nv_bfloat16* Cl0, float* Cf0, int K0,
               const __nv_bfloat16* __restrict__ Ah1, const __nv_bfloat16* __restrict__ Al1,
               const __nv_bfloat16* __restrict__ Bh1, const __nv_bfloat16* __restrict__ Bl1,
               const float* __restrict__ bias1,
               __nv_bfloat16* Ch1, __nv_bfloat16* Cl1, float* Cf1, int K1,
               int lda, int ldc)
{
    extern __shared__ char smem[];
    const uint32_t sb = smem_u32(smem);
    const int tid  = threadIdx.x;
    const int wid  = tid >> 5;
    const int lane = tid & 31;
    const int wm   = wid >> 1;          // 0..3  (32-row slab)
    const int wn   = wid & 1;           // 0..1  (32-col slab)
    const int m0   = blockIdx.y * 128;
    const int n0   = blockIdx.x * 64;

    // per-z job select
    const int zz = blockIdx.z;
    const __nv_bfloat16* Ah = zz ? Ah1 : Ah0;
    const __nv_bfloat16* Al = zz ? Al1 : Al0;
    const __nv_bfloat16* Bh = zz ? Bh1 : Bh0;
    const __nv_bfloat16* Bl = zz ? Bl1 : Bl0;
    const float*       bias = zz ? bias1 : bias0;
    __nv_bfloat16*       Ch = zz ? Ch1 : Ch0;
    __nv_bfloat16*       Cl = zz ? Cl1 : Cl0;
    float*               Cf = zz ? Cf1 : Cf0;
    const int             K = zz ? K1  : K0;

    // ---- cp.async copy mapping ----
    // A: 128 rows x 64B; thread -> (row = tid>>1, 32B half = tid&1), 2x16B each
    const int crow  = tid >> 1;
    const int chalf = tid & 1;
    const uint32_t csw = (uint32_t)((crow & 6) << 3);
    const uint32_t cd0 = (uint32_t)(crow * 64) + (((uint32_t)(chalf * 32) + 0u)  ^ csw);
    const uint32_t cd1 = (uint32_t)(crow * 64) + (((uint32_t)(chalf * 32) + 16u) ^ csw);
    // B: 64 rows x 64B; thread -> (row = tid>>2, 16B chunk = tid&3), 1x16B each
    const int brow = tid >> 2;
    const int bk16 = tid & 3;
    const uint32_t bd = (uint32_t)(brow * 64) + (((uint32_t)(bk16 * 16)) ^ (uint32_t)((brow & 6) << 3));

    const __nv_bfloat16* gAh = Ah + (size_t)(m0 + crow) * lda + chalf * 16;
    const __nv_bfloat16* gAl = Al + (size_t)(m0 + crow) * lda + chalf * 16;
    const __nv_bfloat16* gBh = Bh + (size_t)(n0 + brow) * K   + bk16 * 8;
    const __nv_bfloat16* gBl = Bl + (size_t)(n0 + brow) * K   + bk16 * 8;

    // ---- ldmatrix fragment addressing ----
    const int g  = lane >> 3;
    const int l8 = lane & 7;
    const uint32_t fsw = (uint32_t)((l8 & 6) << 3);
    const uint32_t a_row = (uint32_t)(wm * 32 + (g & 1) * 8 + l8);
    const uint32_t b_row = (uint32_t)(wn * 32 + (g >> 1) * 8 + l8);
    uint32_t aCk[2], bCk[2];
    #pragma unroll
    for (int ka = 0; ka < 2; ++ka) {
        aCk[ka] = ((uint32_t)((g >> 1) * 16 + ka * 32)) ^ fsw;
        bCk[ka] = ((uint32_t)((g & 1)  * 16 + ka * 32)) ^ fsw;
    }
    const uint32_t aBase = a_row * 64u;
    const uint32_t bBase = b_row * 64u;

    float acc[2][4][4];
    #pragma unroll
    for (int i = 0; i < 2; ++i)
        #pragma unroll
        for (int j = 0; j < 4; ++j)
            #pragma unroll
            for (int r = 0; r < 4; ++r) acc[i][j][r] = 0.f;

    const int NC = K / BK;

    // prologue: stage chunks 0,1
    #pragma unroll
    for (int p = 0; p < 2; ++p) {
        uint32_t st = sb + (uint32_t)p * STAGE;
        const int kc = p * BK;
        cpasync16(st + AH_OFF + cd0, gAh + kc);
        cpasync16(st + AH_OFF + cd1, gAh + kc + 8);
        cpasync16(st + AL_OFF + cd0, gAl + kc);
        cpasync16(st + AL_OFF + cd1, gAl + kc + 8);
        cpasync16(st + BH_OFF + bd,  gBh + kc);
        cpasync16(st + BL_OFF + bd,  gBl + kc);
        cp_commit();
    }

    int s_cons = 0;   // stage of chunk c
    int s_load = 2;   // stage of chunk c+2
    for (int c = 0; c < NC; ++c) {
        cp_wait1();                          // chunk c complete
        __syncthreads();                     // visibility + all warps done with chunk c-1

        if (c + 2 < NC) {
            const int kc = (c + 2) * BK;
            uint32_t st = sb + (uint32_t)s_load * STAGE;
            cpasync16(st + AH_OFF + cd0, gAh + kc);
            cpasync16(st + AH_OFF + cd1, gAh + kc + 8);
            cpasync16(st + AL_OFF + cd0, gAl + kc);
            cpasync16(st + AL_OFF + cd1, gAl + kc + 8);
            cpasync16(st + BH_OFF + bd,  gBh + kc);
            cpasync16(st + BL_OFF + bd,  gBl + kc);
        }
        cp_commit();

        const uint32_t st = sb + (uint32_t)s_cons * STAGE;
        #pragma unroll
        for (int ka = 0; ka < 2; ++ka) {
            uint32_t bhf[2][4], blf[2][4];
            ldsm4(bhf[0], st + BH_OFF + bBase +    0u + bCk[ka]);
            ldsm4(bhf[1], st + BH_OFF + bBase + 1024u + bCk[ka]);
            ldsm4(blf[0], st + BL_OFF + bBase +    0u + bCk[ka]);
            ldsm4(blf[1], st + BL_OFF + bBase + 1024u + bCk[ka]);
            uint32_t af[2][4], alf[2][4];
            ldsm4(af[0],  st + AH_OFF + aBase +    0u + aCk[ka]);
            ldsm4(af[1],  st + AH_OFF + aBase + 1024u + aCk[ka]);
            ldsm4(alf[0], st + AL_OFF + aBase +    0u + aCk[ka]);
            ldsm4(alf[1], st + AL_OFF + aBase + 1024u + aCk[ka]);
            #pragma unroll
            for (int i = 0; i < 2; ++i) {
                #pragma unroll
                for (int j = 0; j < 4; ++j) {
                    const uint32_t b0h = bhf[j >> 1][(j & 1) * 2];
                    const uint32_t b1h = bhf[j >> 1][(j & 1) * 2 + 1];
                    const uint32_t b0l = blf[j >> 1][(j & 1) * 2];
                    const uint32_t b1l = blf[j >> 1][(j & 1) * 2 + 1];
                    mma16816(acc[i][j], af[i],  b0h, b1h);
                    mma16816(acc[i][j], af[i],  b0l, b1l);
                    mma16816(acc[i][j], alf[i], b0h, b1h);
                }
            }
        }
        if (++s_cons == NSTAGE) s_cons = 0;
        if (++s_load == NSTAGE) s_load = 0;
    }

    // ---- epilogue ----
    const int quad = lane >> 2;
    const int tq   = lane & 3;
    #pragma unroll
    for (int i = 0; i < 2; ++i) {
        #pragma unroll
        for (int j = 0; j < 4; ++j) {
            const int m = m0 + wm * 32 + i * 16 + quad;
            const int cc = n0 + wn * 32 + j * 8 + tq * 2;
            const float bb0 = __ldg(bias + cc);
            const float bb1 = __ldg(bias + cc + 1);
            if (ACT) {
                float v00 = tanhf(acc[i][j][0] + bb0);
                float v01 = tanhf(acc[i][j][1] + bb1);
                float v10 = tanhf(acc[i][j][2] + bb0);
                float v11 = tanhf(acc[i][j][3] + bb1);
                __nv_bfloat16 h00, l00, h01, l01, h10, l10, h11, l11;
                split_bf16(v00, h00, l00); split_bf16(v01, h01, l01);
                split_bf16(v10, h10, l10); split_bf16(v11, h11, l11);
                __nv_bfloat162 hp0; hp0.x = h00; hp0.y = h01;
                __nv_bfloat162 lp0; lp0.x = l00; lp0.y = l01;
                __nv_bfloat162 hp1; hp1.x = h10; hp1.y = h11;
                __nv_bfloat162 lp1; lp1.x = l10; lp1.y = l11;
                *reinterpret_cast<__nv_bfloat162*>(Ch + (size_t)m * ldc + cc)       = hp0;
                *reinterpret_cast<__nv_bfloat162*>(Cl + (size_t)m * ldc + cc)       = lp0;
                *reinterpret_cast<__nv_bfloat162*>(Ch + (size_t)(m + 8) * ldc + cc) = hp1;
                *reinterpret_cast<__nv_bfloat162*>(Cl + (size_t)(m + 8) * ldc + cc) = lp1;
            } else {
                float2 v0; v0.x = acc[i][j][0] + bb0; v0.y = acc[i][j][1] + bb1;
                float2 v1; v1.x = acc[i][j][2] + bb0; v1.y = acc[i][j][3] + bb1;
                *reinterpret_cast<float2*>(Cf + (size_t)m * ldc + cc)       = v0;
                *reinterpret_cast<float2*>(Cf + (size_t)(m + 8) * ldc + cc) = v1;
            }
        }
    }
}

// ---------------------------------------------------------------------------
// K5: per-row epilogue
// ---------------------------------------------------------------------------
__global__ void final_kernel(const float* __restrict__ z,
                             const float* __restrict__ inv_mass,
                             const float* __restrict__ diffusion,
                             float* __restrict__ out)
{
    int row = blockIdx.x;
    int j   = threadIdx.x;

    float p1  = g_P1[(long)row * LD + j];
    float p2  = g_P2[(long)row * LD + j];
    float dif = diffusion[j];

    float sgn  = (dif > 0.f) ? 1.f : ((dif < 0.f) ? -1.f : 0.f);
    float sden = (fabsf(dif) > 1e-7f) ? dif : sgn * 1e-7f;
    float r    = (p1 - p2) / sden;
    float sq   = r * r;

    __shared__ float wsum[8];
    #pragma unroll
    for (int off = 16; off > 0; off >>= 1)
        sq += __shfl_down_sync(0xffffffffu, sq, off);
    if ((j & 31) == 0) wsum[j >> 5] = sq;
    __syncthreads();

    long dbase = (long)row * OUTC;
    long obase = (long)NB * OUTC + dbase;

    if (j == 0) {
        float s = 0.f;
        #pragma unroll
        for (int w = 0; w < 8; ++w) s += wsum[w];
        out[dbase + 512] = s;
        out[obase + 512] = 0.f;
    }
    float mom = z[(long)row * ZLD + 256 + j];
    out[dbase + j]       = inv_mass[j] * mom;
    out[dbase + 256 + j] = p2;
    out[obase + j]       = 0.f;
    out[obase + 256 + j] = dif;
}

// ---------------------------------------------------------------------------
extern "C" void kernel_launch(void* const* d_in, const int* in_sizes, int n_in,
                              void* d_out, int out_size)
{
    const float* z    = (const float*)d_in[0];
    const float* ts   = (const float*)d_in[1];
    const float* t    = (const float*)d_in[2];
    const float* ctx  = (const float*)d_in[3];
    const float* im   = (const float*)d_in[4];
    const float* dif  = (const float*)d_in[5];
    const float* Wc1  = (const float*)d_in[6];
    const float* bc1  = (const float*)d_in[7];
    const float* Wc2  = (const float*)d_in[8];
    const float* bc2  = (const float*)d_in[9];
    const float* Wh1  = (const float*)d_in[10];
    const float* bh1  = (const float*)d_in[11];
    const float* Wh2  = (const float*)d_in[12];
    const float* bh2  = (const float*)d_in[13];
    float* out = (float*)d_out;

    __nv_bfloat16 *pXh, *pXl, *pH1h, *pH1l, *pH2h, *pH2l;
    __nv_bfloat16 *pWh1h, *pWh1l, *pWc1h, *pWc1l, *pWh2h, *pWh2l, *pWc2h, *pWc2l;
    float *pP1, *pP2;
    cudaGetSymbolAddress((void**)&pXh,  g_Xh);   cudaGetSymbolAddress((void**)&pXl,  g_Xl);
    cudaGetSymbolAddress((void**)&pH1h, g_H1h);  cudaGetSymbolAddress((void**)&pH1l, g_H1l);
    cudaGetSymbolAddress((void**)&pH2h, g_H2h);  cudaGetSymbolAddress((void**)&pH2l, g_H2l);
    cudaGetSymbolAddress((void**)&pP1,  g_P1);   cudaGetSymbolAddress((void**)&pP2,  g_P2);
    cudaGetSymbolAddress((void**)&pWh1h, g_Wh1h); cudaGetSymbolAddress((void**)&pWh1l, g_Wh1l);
    cudaGetSymbolAddress((void**)&pWc1h, g_Wc1h); cudaGetSymbolAddress((void**)&pWc1l, g_Wc1l);
    cudaGetSymbolAddress((void**)&pWh2h, g_Wh2h); cudaGetSymbolAddress((void**)&pWh2l, g_Wh2l);
    cudaGetSymbolAddress((void**)&pWc2h, g_Wc2h); cudaGetSymbolAddress((void**)&pWc2l, g_Wc2l);

    const int smem_bytes = NSTAGE * STAGE;   // 72 KB
    cudaFuncSetAttribute(mma_gemm2<1>, cudaFuncAttributeMaxDynamicSharedMemorySize, smem_bytes);
    cudaFuncSetAttribute(mma_gemm2<0>, cudaFuncAttributeMaxDynamicSharedMemorySize, smem_bytes);

    // weight prep: all 4 transpose+split jobs in one launch
    wsplit_all<<<dim3(32, 32, 4), dim3(32, 32)>>>(
        Wh1, Wc1, Wh2, Wc2,
        pWh1h, pWh1l, pWc1h, pWc1l, pWh2h, pWh2l, pWc2h, pWc2l);

    // X build (bf16 hi/lo)
    prep_kernel<<<(NB * XK) / 256, 256>>>(z, ctx, ts, t);

    // Layer 1 (batched): z=0 H1 = tanh(pm@Wh1+bh1) K=512 ; z=1 H2 = tanh(X@Wc1+bc1) K=1024
    mma_gemm2<1><<<dim3(HD / 64, NB / 128, 2), 256, smem_bytes>>>(
        pXh, pXl, pWh1h, pWh1l, bh1, pH1h, pH1l, nullptr, 512,
        pXh, pXl, pWc1h, pWc1l, bc1, pH2h, pH2l, nullptr, 1024,
        XK, HD);

    // Layer 2 (batched): z=0 P1 = H1@Wh2+bh2 ; z=1 P2 = H2@Wc2+bc2   (N=256)
    mma_gemm2<0><<<dim3(LD / 64, NB / 128, 2), 256, smem_bytes>>>(
        pH1h, pH1l, pWh2h, pWh2l, bh2, nullptr, nullptr, pP1, 1024,
        pH2h, pH2l, pWc2h, pWc2l, bc2, nullptr, nullptr, pP2, 1024,
        HD, LD);

    final_kernel<<<NB, 256>>>(z, im, dif, out);
}

// round 10
// speedup vs baseline: 1.4432x; 1.4432x over previous
#include <cuda_runtime.h>
#include <cuda_fp16.h>
#include <cstdint>
#include <math.h>

// ---------------- problem constants ----------------
#define NB   16384
#define ZLD  513
#define XK   1024
#define HD   1024
#define LD   256
#define OUTC 513

// ---------------- scratch ----------------
__device__ __half g_X [NB * XK];     // activations (single fp16)
__device__ __half g_H1[NB * HD];
__device__ __half g_H2[NB * HD];
__device__ float  g_P1[NB * LD];
__device__ float  g_P2[NB * LD];
// transposed + fp16-split weights: Wt[n*K+k] = W[k*N+n],  W = hi + lo (exact to 22 bits)
__device__ __half g_Wh1h[HD * 512], g_Wh1l[HD * 512];
__device__ __half g_Wc1h[HD * XK],  g_Wc1l[HD * XK];
__device__ __half g_Wh2h[LD * HD],  g_Wh2l[LD * HD];
__device__ __half g_Wc2h[LD * HD],  g_Wc2l[LD * HD];

// ---------------- helpers ----------------
__device__ __forceinline__ uint32_t smem_u32(const void* p) {
    uint32_t a;
    asm("{ .reg .u64 t; cvta.to.shared.u64 t, %1; cvt.u32.u64 %0, t; }" : "=r"(a) : "l"(p));
    return a;
}
__device__ __forceinline__ void ldsm4(uint32_t (&r)[4], uint32_t addr) {
    asm volatile("ldmatrix.sync.aligned.m8n8.x4.shared.b16 {%0,%1,%2,%3}, [%4];"
        : "=r"(r[0]), "=r"(r[1]), "=r"(r[2]), "=r"(r[3]) : "r"(addr));
}
__device__ __forceinline__ void mma16816(float (&d)[4], const uint32_t (&a)[4],
                                         uint32_t b0, uint32_t b1) {
    asm volatile("mma.sync.aligned.m16n8k16.row.col.f32.f16.f16.f32 "
        "{%0,%1,%2,%3}, {%4,%5,%6,%7}, {%8,%9}, {%0,%1,%2,%3};"
        : "+f"(d[0]), "+f"(d[1]), "+f"(d[2]), "+f"(d[3])
        : "r"(a[0]), "r"(a[1]), "r"(a[2]), "r"(a[3]), "r"(b0), "r"(b1));
}
__device__ __forceinline__ void cpasync16(uint32_t saddr, const void* g) {
    asm volatile("cp.async.cg.shared.global [%0], [%1], 16;" :: "r"(saddr), "l"(g));
}
__device__ __forceinline__ void cp_commit() { asm volatile("cp.async.commit_group;"); }
__device__ __forceinline__ void cp_wait1()  { asm volatile("cp.async.wait_group 1;"  ::: "memory"); }

__device__ __forceinline__ void split_fp16(float v, __half& hi, __half& lo) {
    hi = __float2half_rn(v);
    lo = __float2half_rn(v - __half2float(hi));
}

// ---------------------------------------------------------------------------
// K0: X = [ z[:, :512] , ctx[:, i, :] ]  -> fp16
// ---------------------------------------------------------------------------
__global__ void prep_kernel(const float* __restrict__ z,
                            const float* __restrict__ ctx,
                            const float* __restrict__ ts,
                            const float* __restrict__ tp)
{
    int idx = blockIdx.x * blockDim.x + threadIdx.x;
    float t = tp[0];
    int i = 0;
    #pragma unroll
    for (int j = 0; j < 16; ++j) i += (ts[j] <= t) ? 1 : 0;
    if (i > 15) i = 15;
    int row = idx >> 10, c = idx & 1023;
    float v = (c < 512) ? z[(long)row * ZLD + c]
                        : ctx[((long)row * 16 + i) * 512 + (c - 512)];
    g_X[idx] = __float2half_rn(v);
}

// ---------------------------------------------------------------------------
// All 4 weight transposes + fp16 hi/lo splits in ONE launch (job = blockIdx.z)
// ---------------------------------------------------------------------------
__global__ void wsplit_all(const float* __restrict__ Wh1, const float* __restrict__ Wc1,
                           const float* __restrict__ Wh2, const float* __restrict__ Wc2,
                           __half* Th1, __half* Tl1,
                           __half* Tc1h, __half* Tc1l,
                           __half* Th2, __half* Tl2,
                           __half* Tc2h, __half* Tc2l)
{
    const float* W; int K, N; __half *Th, *Tl;
    switch (blockIdx.z) {
        case 0: W = Wh1; K = 512;  N = HD; Th = Th1;  Tl = Tl1;  break;
        case 1: W = Wc1; K = XK;   N = HD; Th = Tc1h; Tl = Tc1l; break;
        case 2: W = Wh2; K = HD;   N = LD; Th = Th2;  Tl = Tl2;  break;
        default:W = Wc2; K = HD;   N = LD; Th = Tc2h; Tl = Tc2l; break;
    }
    if ((int)(blockIdx.x * 32) >= N || (int)(blockIdx.y * 32) >= K) return;

    __shared__ float s[32][33];
    int k = blockIdx.y * 32 + threadIdx.y;
    int n = blockIdx.x * 32 + threadIdx.x;
    s[threadIdx.y][threadIdx.x] = W[(long)k * N + n];
    __syncthreads();
    int nn = blockIdx.x * 32 + threadIdx.y;
    int kk = blockIdx.y * 32 + threadIdx.x;
    float v = s[threadIdx.x][threadIdx.y];
    __half hi, lo; split_fp16(v, hi, lo);
    Th[(long)nn * K + kk] = hi;
    Tl[(long)nn * K + kk] = lo;
}

// ---------------------------------------------------------------------------
// mma.sync fp16 GEMM, weight hi/lo split (2-term): C = act(A @ (Wh+Wl)^T + bias)
//   A : [M][lda] fp16 (single),   B(=Wt) : [N][K] fp16 hi/lo
// CTA tile 128x128, BK=32, 256 thr / 8 warps (warp tile 64x32), batched blockIdx.z.
// 3-stage cp.async pipeline, one barrier per chunk.
// Stage layout: A 8K | B_h 8K | B_l 8K  (rows 64B, XOR swizzle). 72KB total.
// ---------------------------------------------------------------------------
#define BK      32
#define A_OFF   0u
#define BH_OFF  8192u
#define BL_OFF  16384u
#define STAGE   24576
#define NSTAGE  3

template<int ACT>
__global__ __launch_bounds__(256, 2)
void mma_gemm2(const __half* __restrict__ A0,
               const __half* __restrict__ Bh0, const __half* __restrict__ Bl0,
               const float* __restrict__ bias0,
               __half* C0, float* Cf0, int K0,
               const __half* __restrict__ A1,
               const __half* __restrict__ Bh1, const __half* __restrict__ Bl1,
               const float* __restrict__ bias1,
               __half* C1, float* Cf1, int K1,
               int lda, int ldc)
{
    extern __shared__ char smem[];
    const uint32_t sb = smem_u32(smem);
    const int tid  = threadIdx.x;
    const int wid  = tid >> 5;
    const int lane = tid & 31;
    const int wm   = wid >> 2;          // 0..1  (64-row slab)
    const int wn   = wid & 3;           // 0..3  (32-col slab)
    const int m0   = blockIdx.y * 128;
    const int n0   = blockIdx.x * 128;

    // per-z job select
    const int zz = blockIdx.z;
    const __half*  A   = zz ? A1   : A0;
    const __half*  Bh  = zz ? Bh1  : Bh0;
    const __half*  Bl  = zz ? Bl1  : Bl0;
    const float*  bias = zz ? bias1 : bias0;
    __half*        C   = zz ? C1   : C0;
    float*         Cf  = zz ? Cf1  : Cf0;
    const int      K   = zz ? K1   : K0;

    // ---- cp.async copy mapping: thread -> (row = tid>>1, 32B half = tid&1) ----
    const int crow  = tid >> 1;
    const int chalf = tid & 1;
    const uint32_t csw = (uint32_t)((crow & 6) << 3);
    const uint32_t cd0 = (uint32_t)(crow * 64) + (((uint32_t)(chalf * 32) + 0u)  ^ csw);
    const uint32_t cd1 = (uint32_t)(crow * 64) + (((uint32_t)(chalf * 32) + 16u) ^ csw);

    const __half* gA  = A  + (size_t)(m0 + crow) * lda + chalf * 16;
    const __half* gBh = Bh + (size_t)(n0 + crow) * K   + chalf * 16;
    const __half* gBl = Bl + (size_t)(n0 + crow) * K   + chalf * 16;

    // ---- ldmatrix fragment addressing ----
    const int g  = lane >> 3;
    const int l8 = lane & 7;
    const uint32_t fsw = (uint32_t)((l8 & 6) << 3);
    const uint32_t a_row = (uint32_t)(wm * 64 + (g & 1) * 8 + l8);
    const uint32_t b_row = (uint32_t)(wn * 32 + (g >> 1) * 8 + l8);
    uint32_t aCk[2], bCk[2];
    #pragma unroll
    for (int ka = 0; ka < 2; ++ka) {
        aCk[ka] = ((uint32_t)((g >> 1) * 16 + ka * 32)) ^ fsw;
        bCk[ka] = ((uint32_t)((g & 1)  * 16 + ka * 32)) ^ fsw;
    }
    const uint32_t aBase = a_row * 64u;
    const uint32_t bBase = b_row * 64u;

    float acc[4][4][4];
    #pragma unroll
    for (int i = 0; i < 4; ++i)
        #pragma unroll
        for (int j = 0; j < 4; ++j)
            #pragma unroll
            for (int r = 0; r < 4; ++r) acc[i][j][r] = 0.f;

    const int NC = K / BK;

    // prologue: stage chunks 0,1
    #pragma unroll
    for (int p = 0; p < 2; ++p) {
        uint32_t st = sb + (uint32_t)p * STAGE;
        const int kc = p * BK;
        cpasync16(st + A_OFF  + cd0, gA  + kc);
        cpasync16(st + A_OFF  + cd1, gA  + kc + 8);
        cpasync16(st + BH_OFF + cd0, gBh + kc);
        cpasync16(st + BH_OFF + cd1, gBh + kc + 8);
        cpasync16(st + BL_OFF + cd0, gBl + kc);
        cpasync16(st + BL_OFF + cd1, gBl + kc + 8);
        cp_commit();
    }

    int s_cons = 0;   // stage of chunk c
    int s_load = 2;   // stage of chunk c+2
    for (int c = 0; c < NC; ++c) {
        cp_wait1();                          // chunk c complete
        __syncthreads();                     // visibility + all warps done with chunk c-1

        if (c + 2 < NC) {
            const int kc = (c + 2) * BK;
            uint32_t st = sb + (uint32_t)s_load * STAGE;
            cpasync16(st + A_OFF  + cd0, gA  + kc);
            cpasync16(st + A_OFF  + cd1, gA  + kc + 8);
            cpasync16(st + BH_OFF + cd0, gBh + kc);
            cpasync16(st + BH_OFF + cd1, gBh + kc + 8);
            cpasync16(st + BL_OFF + cd0, gBl + kc);
            cpasync16(st + BL_OFF + cd1, gBl + kc + 8);
        }
        cp_commit();

        // consume chunk c
        const uint32_t st = sb + (uint32_t)s_cons * STAGE;
        uint32_t bh[2][2][4], bl[2][2][4];
        #pragma unroll
        for (int ka = 0; ka < 2; ++ka) {
            ldsm4(bh[ka][0], st + BH_OFF + bBase +    0u + bCk[ka]);
            ldsm4(bh[ka][1], st + BH_OFF + bBase + 1024u + bCk[ka]);
            ldsm4(bl[ka][0], st + BL_OFF + bBase +    0u + bCk[ka]);
            ldsm4(bl[ka][1], st + BL_OFF + bBase + 1024u + bCk[ka]);
        }
        #pragma unroll
        for (int i = 0; i < 4; ++i) {
            uint32_t af[2][4];
            ldsm4(af[0], st + A_OFF + aBase + (uint32_t)(i * 1024) + aCk[0]);
            ldsm4(af[1], st + A_OFF + aBase + (uint32_t)(i * 1024) + aCk[1]);
            #pragma unroll
            for (int ka = 0; ka < 2; ++ka) {
                #pragma unroll
                for (int j = 0; j < 4; ++j) {
                    const uint32_t b0h = bh[ka][j >> 1][(j & 1) * 2];
                    const uint32_t b1h = bh[ka][j >> 1][(j & 1) * 2 + 1];
                    const uint32_t b0l = bl[ka][j >> 1][(j & 1) * 2];
                    const uint32_t b1l = bl[ka][j >> 1][(j & 1) * 2 + 1];
                    mma16816(acc[i][j], af[ka], b0h, b1h);
                    mma16816(acc[i][j], af[ka], b0l, b1l);
                }
            }
        }
        if (++s_cons == NSTAGE) s_cons = 0;
        if (++s_load == NSTAGE) s_load = 0;
    }

    // ---- epilogue ----
    const int quad = lane >> 2;
    const int tq   = lane & 3;
    #pragma unroll
    for (int i = 0; i < 4; ++i) {
        #pragma unroll
        for (int j = 0; j < 4; ++j) {
            const int m = m0 + wm * 64 + i * 16 + quad;
            const int cc = n0 + wn * 32 + j * 8 + tq * 2;
            const float bb0 = __ldg(bias + cc);
            const float bb1 = __ldg(bias + cc + 1);
            if (ACT) {
                float v00 = tanhf(acc[i][j][0] + bb0);
                float v01 = tanhf(acc[i][j][1] + bb1);
                float v10 = tanhf(acc[i][j][2] + bb0);
                float v11 = tanhf(acc[i][j][3] + bb1);
                __half2 p0; p0.x = __float2half_rn(v00); p0.y = __float2half_rn(v01);
                __half2 p1; p1.x = __float2half_rn(v10); p1.y = __float2half_rn(v11);
                *reinterpret_cast<__half2*>(C + (size_t)m * ldc + cc)       = p0;
                *reinterpret_cast<__half2*>(C + (size_t)(m + 8) * ldc + cc) = p1;
            } else {
                float2 v0; v0.x = acc[i][j][0] + bb0; v0.y = acc[i][j][1] + bb1;
                float2 v1; v1.x = acc[i][j][2] + bb0; v1.y = acc[i][j][3] + bb1;
                *reinterpret_cast<float2*>(Cf + (size_t)m * ldc + cc)       = v0;
                *reinterpret_cast<float2*>(Cf + (size_t)(m + 8) * ldc + cc) = v1;
            }
        }
    }
}

// ---------------------------------------------------------------------------
// K5: per-row epilogue
// ---------------------------------------------------------------------------
__global__ void final_kernel(const float* __restrict__ z,
                             const float* __restrict__ inv_mass,
                             const float* __restrict__ diffusion,
                             float* __restrict__ out)
{
    int row = blockIdx.x;
    int j   = threadIdx.x;

    float p1  = g_P1[(long)row * LD + j];
    float p2  = g_P2[(long)row * LD + j];
    float dif = diffusion[j];

    float sgn  = (dif > 0.f) ? 1.f : ((dif < 0.f) ? -1.f : 0.f);
    float sden = (fabsf(dif) > 1e-7f) ? dif : sgn * 1e-7f;
    float r    = (p1 - p2) / sden;
    float sq   = r * r;

    __shared__ float wsum[8];
    #pragma unroll
    for (int off = 16; off > 0; off >>= 1)
        sq += __shfl_down_sync(0xffffffffu, sq, off);
    if ((j & 31) == 0) wsum[j >> 5] = sq;
    __syncthreads();

    long dbase = (long)row * OUTC;
    long obase = (long)NB * OUTC + dbase;

    if (j == 0) {
        float s = 0.f;
        #pragma unroll
        for (int w = 0; w < 8; ++w) s += wsum[w];
        out[dbase + 512] = s;
        out[obase + 512] = 0.f;
    }
    float mom = z[(long)row * ZLD + 256 + j];
    out[dbase + j]       = inv_mass[j] * mom;
    out[dbase + 256 + j] = p2;
    out[obase + j]       = 0.f;
    out[obase + 256 + j] = dif;
}

// ---------------------------------------------------------------------------
extern "C" void kernel_launch(void* const* d_in, const int* in_sizes, int n_in,
                              void* d_out, int out_size)
{
    const float* z    = (const float*)d_in[0];
    const float* ts   = (const float*)d_in[1];
    const float* t    = (const float*)d_in[2];
    const float* ctx  = (const float*)d_in[3];
    const float* im   = (const float*)d_in[4];
    const float* dif  = (const float*)d_in[5];
    const float* Wc1  = (const float*)d_in[6];
    const float* bc1  = (const float*)d_in[7];
    const float* Wc2  = (const float*)d_in[8];
    const float* bc2  = (const float*)d_in[9];
    const float* Wh1  = (const float*)d_in[10];
    const float* bh1  = (const float*)d_in[11];
    const float* Wh2  = (const float*)d_in[12];
    const float* bh2  = (const float*)d_in[13];
    float* out = (float*)d_out;

    __half *pX, *pH1, *pH2;
    __half *pWh1h, *pWh1l, *pWc1h, *pWc1l, *pWh2h, *pWh2l, *pWc2h, *pWc2l;
    float *pP1, *pP2;
    cudaGetSymbolAddress((void**)&pX,  g_X);
    cudaGetSymbolAddress((void**)&pH1, g_H1);
    cudaGetSymbolAddress((void**)&pH2, g_H2);
    cudaGetSymbolAddress((void**)&pP1, g_P1);
    cudaGetSymbolAddress((void**)&pP2, g_P2);
    cudaGetSymbolAddress((void**)&pWh1h, g_Wh1h); cudaGetSymbolAddress((void**)&pWh1l, g_Wh1l);
    cudaGetSymbolAddress((void**)&pWc1h, g_Wc1h); cudaGetSymbolAddress((void**)&pWc1l, g_Wc1l);
    cudaGetSymbolAddress((void**)&pWh2h, g_Wh2h); cudaGetSymbolAddress((void**)&pWh2l, g_Wh2l);
    cudaGetSymbolAddress((void**)&pWc2h, g_Wc2h); cudaGetSymbolAddress((void**)&pWc2l, g_Wc2l);

    const int smem_bytes = NSTAGE * STAGE;   // 72 KB
    cudaFuncSetAttribute(mma_gemm2<1>, cudaFuncAttributeMaxDynamicSharedMemorySize, smem_bytes);
    cudaFuncSetAttribute(mma_gemm2<0>, cudaFuncAttributeMaxDynamicSharedMemorySize, smem_bytes);

    // weight prep: all 4 transpose+split jobs in one launch
    wsplit_all<<<dim3(32, 32, 4), dim3(32, 32)>>>(
        Wh1, Wc1, Wh2, Wc2,
        pWh1h, pWh1l, pWc1h, pWc1l, pWh2h, pWh2l, pWc2h, pWc2l);

    // X build (fp16)
    prep_kernel<<<(NB * XK) / 256, 256>>>(z, ctx, ts, t);

    // Layer 1 (batched): z=0 H1 = tanh(pm@Wh1+bh1) K=512 ; z=1 H2 = tanh(X@Wc1+bc1) K=1024
    mma_gemm2<1><<<dim3(HD / 128, NB / 128, 2), 256, smem_bytes>>>(
        pX, pWh1h, pWh1l, bh1, pH1, nullptr, 512,
        pX, pWc1h, pWc1l, bc1, pH2, nullptr, 1024,
        XK, HD);

    // Layer 2 (batched): z=0 P1 = H1@Wh2+bh2 ; z=1 P2 = H2@Wc2+bc2   (N=256)
    mma_gemm2<0><<<dim3(LD / 128, NB / 128, 2), 256, smem_bytes>>>(
        pH1, pWh2h, pWh2l, bh2, nullptr, pP1, 1024,
        pH2, pWc2h, pWc2l, bc2, nullptr, pP2, 1024,
        HD, LD);

    final_kernel<<<NB, 256>>>(z, im, dif, out);
}

// round 11
// speedup vs baseline: 2.1270x; 1.4737x over previous
#include <cuda_runtime.h>
#include <cuda_fp16.h>
#include <cstdint>
#include <math.h>

// ---------------- problem constants ----------------
#define NB   16384
#define ZLD  513
#define XK   1024
#define HD   1024
#define LD   256
#define OUTC 513

// ---------------- scratch ----------------
__device__ __half g_X [NB * XK];     // activations fp16
__device__ __half g_H1[NB * HD];
__device__ __half g_H2[NB * HD];
__device__ float  g_P1[NB * LD];
__device__ float  g_P2[NB * LD];
// transposed fp16 weights: Wt[n*K+k] = W[k*N+n]
__device__ __half g_Wh1[HD * 512];
__device__ __half g_Wc1[HD * XK];
__device__ __half g_Wh2[LD * HD];
__device__ __half g_Wc2[LD * HD];

// ---------------- helpers ----------------
__device__ __forceinline__ uint32_t smem_u32(const void* p) {
    uint32_t a;
    asm("{ .reg .u64 t; cvta.to.shared.u64 t, %1; cvt.u32.u64 %0, t; }" : "=r"(a) : "l"(p));
    return a;
}
__device__ __forceinline__ void ldsm4(uint32_t (&r)[4], uint32_t addr) {
    asm volatile("ldmatrix.sync.aligned.m8n8.x4.shared.b16 {%0,%1,%2,%3}, [%4];"
        : "=r"(r[0]), "=r"(r[1]), "=r"(r[2]), "=r"(r[3]) : "r"(addr));
}
__device__ __forceinline__ void mma16816(float (&d)[4], const uint32_t (&a)[4],
                                         uint32_t b0, uint32_t b1) {
    asm volatile("mma.sync.aligned.m16n8k16.row.col.f32.f16.f16.f32 "
        "{%0,%1,%2,%3}, {%4,%5,%6,%7}, {%8,%9}, {%0,%1,%2,%3};"
        : "+f"(d[0]), "+f"(d[1]), "+f"(d[2]), "+f"(d[3])
        : "r"(a[0]), "r"(a[1]), "r"(a[2]), "r"(a[3]), "r"(b0), "r"(b1));
}
__device__ __forceinline__ void cpasync16(uint32_t saddr, const void* g) {
    asm volatile("cp.async.cg.shared.global [%0], [%1], 16;" :: "r"(saddr), "l"(g));
}
__device__ __forceinline__ void cp_commit() { asm volatile("cp.async.commit_group;"); }
__device__ __forceinline__ void cp_wait1()  { asm volatile("cp.async.wait_group 1;"  ::: "memory"); }

// ---------------------------------------------------------------------------
// K0: X = [ z[:, :512] , ctx[:, i, :] ]  -> fp16
// ---------------------------------------------------------------------------
__global__ void prep_kernel(const float* __restrict__ z,
                            const float* __restrict__ ctx,
                            const float* __restrict__ ts,
                            const float* __restrict__ tp)
{
    int idx = blockIdx.x * blockDim.x + threadIdx.x;
    float t = tp[0];
    int i = 0;
    #pragma unroll
    for (int j = 0; j < 16; ++j) i += (ts[j] <= t) ? 1 : 0;
    if (i > 15) i = 15;
    int row = idx >> 10, c = idx & 1023;
    float v = (c < 512) ? z[(long)row * ZLD + c]
                        : ctx[((long)row * 16 + i) * 512 + (c - 512)];
    g_X[idx] = __float2half_rn(v);
}

// ---------------------------------------------------------------------------
// All 4 weight transposes (fp32 -> fp16) in ONE launch (job = blockIdx.z)
// ---------------------------------------------------------------------------
__global__ void wtrans_all(const float* __restrict__ Wh1, const float* __restrict__ Wc1,
                           const float* __restrict__ Wh2, const float* __restrict__ Wc2,
                           __half* T1, __half* T2, __half* T3, __half* T4)
{
    const float* W; int K, N; __half *T;
    switch (blockIdx.z) {
        case 0: W = Wh1; K = 512;  N = HD; T = T1; break;
        case 1: W = Wc1; K = XK;   N = HD; T = T2; break;
        case 2: W = Wh2; K = HD;   N = LD; T = T3; break;
        default:W = Wc2; K = HD;   N = LD; T = T4; break;
    }
    if ((int)(blockIdx.x * 32) >= N || (int)(blockIdx.y * 32) >= K) return;

    __shared__ float s[32][33];
    int k = blockIdx.y * 32 + threadIdx.y;
    int n = blockIdx.x * 32 + threadIdx.x;
    s[threadIdx.y][threadIdx.x] = W[(long)k * N + n];
    __syncthreads();
    int nn = blockIdx.x * 32 + threadIdx.y;
    int kk = blockIdx.y * 32 + threadIdx.x;
    T[(long)nn * K + kk] = __float2half_rn(s[threadIdx.x][threadIdx.y]);
}

// ---------------------------------------------------------------------------
// mma.sync fp16 GEMM (single-term): C = act(A @ W^T + bias)
//   A : [M][lda] fp16,   B(=Wt) : [N][K] fp16
// CTA tile 128x128, BK=32, 256 thr / 8 warps (warp tile 64x32), batched blockIdx.z.
// 3-stage cp.async pipeline, one barrier per chunk.
// Stage layout: A 8K | B 8K  (rows 64B, XOR swizzle). 48KB total.
// ---------------------------------------------------------------------------
#define BK      32
#define A_OFF   0u
#define B_OFF   8192u
#define STAGE   16384
#define NSTAGE  3

template<int ACT>
__global__ __launch_bounds__(256, 2)
void mma_gemm2(const __half* __restrict__ A0, const __half* __restrict__ B0,
               const float* __restrict__ bias0,
               __half* C0, float* Cf0, int K0,
               const __half* __restrict__ A1, const __half* __restrict__ B1,
               const float* __restrict__ bias1,
               __half* C1, float* Cf1, int K1,
               int lda, int ldc)
{
    extern __shared__ char smem[];
    const uint32_t sb = smem_u32(smem);
    const int tid  = threadIdx.x;
    const int wid  = tid >> 5;
    const int lane = tid & 31;
    const int wm   = wid >> 2;          // 0..1  (64-row slab)
    const int wn   = wid & 3;           // 0..3  (32-col slab)
    const int m0   = blockIdx.y * 128;
    const int n0   = blockIdx.x * 128;

    // per-z job select
    const int zz = blockIdx.z;
    const __half*  A   = zz ? A1   : A0;
    const __half*  B   = zz ? B1   : B0;
    const float*  bias = zz ? bias1 : bias0;
    __half*        C   = zz ? C1   : C0;
    float*         Cf  = zz ? Cf1  : Cf0;
    const int      K   = zz ? K1   : K0;

    // ---- cp.async copy mapping: thread -> (row = tid>>1, 32B half = tid&1) ----
    const int crow  = tid >> 1;
    const int chalf = tid & 1;
    const uint32_t csw = (uint32_t)((crow & 6) << 3);
    const uint32_t cd0 = (uint32_t)(crow * 64) + (((uint32_t)(chalf * 32) + 0u)  ^ csw);
    const uint32_t cd1 = (uint32_t)(crow * 64) + (((uint32_t)(chalf * 32) + 16u) ^ csw);

    const __half* gA = A + (size_t)(m0 + crow) * lda + chalf * 16;
    const __half* gB = B + (size_t)(n0 + crow) * K   + chalf * 16;

    // ---- ldmatrix fragment addressing ----
    const int g  = lane >> 3;
    const int l8 = lane & 7;
    const uint32_t fsw = (uint32_t)((l8 & 6) << 3);
    const uint32_t a_row = (uint32_t)(wm * 64 + (g & 1) * 8 + l8);
    const uint32_t b_row = (uint32_t)(wn * 32 + (g >> 1) * 8 + l8);
    uint32_t aCk[2], bCk[2];
    #pragma unroll
    for (int ka = 0; ka < 2; ++ka) {
        aCk[ka] = ((uint32_t)((g >> 1) * 16 + ka * 32)) ^ fsw;
        bCk[ka] = ((uint32_t)((g & 1)  * 16 + ka * 32)) ^ fsw;
    }
    const uint32_t aBase = a_row * 64u;
    const uint32_t bBase = b_row * 64u;

    float acc[4][4][4];
    #pragma unroll
    for (int i = 0; i < 4; ++i)
        #pragma unroll
        for (int j = 0; j < 4; ++j)
            #pragma unroll
            for (int r = 0; r < 4; ++r) acc[i][j][r] = 0.f;

    const int NC = K / BK;

    // prologue: stage chunks 0,1
    #pragma unroll
    for (int p = 0; p < 2; ++p) {
        uint32_t st = sb + (uint32_t)p * STAGE;
        const int kc = p * BK;
        cpasync16(st + A_OFF + cd0, gA + kc);
        cpasync16(st + A_OFF + cd1, gA + kc + 8);
        cpasync16(st + B_OFF + cd0, gB + kc);
        cpasync16(st + B_OFF + cd1, gB + kc + 8);
        cp_commit();
    }

    int s_cons = 0;   // stage of chunk c
    int s_load = 2;   // stage of chunk c+2
    for (int c = 0; c < NC; ++c) {
        cp_wait1();                          // chunk c complete
        __syncthreads();                     // visibility + all warps done with chunk c-1

        if (c + 2 < NC) {
            const int kc = (c + 2) * BK;
            uint32_t st = sb + (uint32_t)s_load * STAGE;
            cpasync16(st + A_OFF + cd0, gA + kc);
            cpasync16(st + A_OFF + cd1, gA + kc + 8);
            cpasync16(st + B_OFF + cd0, gB + kc);
            cpasync16(st + B_OFF + cd1, gB + kc + 8);
        }
        cp_commit();

        // consume chunk c
        const uint32_t st = sb + (uint32_t)s_cons * STAGE;
        uint32_t bf[2][2][4];
        #pragma unroll
        for (int ka = 0; ka < 2; ++ka) {
            ldsm4(bf[ka][0], st + B_OFF + bBase +    0u + bCk[ka]);
            ldsm4(bf[ka][1], st + B_OFF + bBase + 1024u + bCk[ka]);
        }
        #pragma unroll
        for (int i = 0; i < 4; ++i) {
            uint32_t af[2][4];
            ldsm4(af[0], st + A_OFF + aBase + (uint32_t)(i * 1024) + aCk[0]);
            ldsm4(af[1], st + A_OFF + aBase + (uint32_t)(i * 1024) + aCk[1]);
            #pragma unroll
            for (int ka = 0; ka < 2; ++ka) {
                #pragma unroll
                for (int j = 0; j < 4; ++j) {
                    const uint32_t b0 = bf[ka][j >> 1][(j & 1) * 2];
                    const uint32_t b1 = bf[ka][j >> 1][(j & 1) * 2 + 1];
                    mma16816(acc[i][j], af[ka], b0, b1);
                }
            }
        }
        if (++s_cons == NSTAGE) s_cons = 0;
        if (++s_load == NSTAGE) s_load = 0;
    }

    // ---- epilogue ----
    const int quad = lane >> 2;
    const int tq   = lane & 3;
    #pragma unroll
    for (int i = 0; i < 4; ++i) {
        #pragma unroll
        for (int j = 0; j < 4; ++j) {
            const int m = m0 + wm * 64 + i * 16 + quad;
            const int cc = n0 + wn * 32 + j * 8 + tq * 2;
            const float bb0 = __ldg(bias + cc);
            const float bb1 = __ldg(bias + cc + 1);
            if (ACT) {
                float v00 = tanhf(acc[i][j][0] + bb0);
                float v01 = tanhf(acc[i][j][1] + bb1);
                float v10 = tanhf(acc[i][j][2] + bb0);
                float v11 = tanhf(acc[i][j][3] + bb1);
                __half2 p0; p0.x = __float2half_rn(v00); p0.y = __float2half_rn(v01);
                __half2 p1; p1.x = __float2half_rn(v10); p1.y = __float2half_rn(v11);
                *reinterpret_cast<__half2*>(C + (size_t)m * ldc + cc)       = p0;
                *reinterpret_cast<__half2*>(C + (size_t)(m + 8) * ldc + cc) = p1;
            } else {
                float2 v0; v0.x = acc[i][j][0] + bb0; v0.y = acc[i][j][1] + bb1;
                float2 v1; v1.x = acc[i][j][2] + bb0; v1.y = acc[i][j][3] + bb1;
                *reinterpret_cast<float2*>(Cf + (size_t)m * ldc + cc)       = v0;
                *reinterpret_cast<float2*>(Cf + (size_t)(m + 8) * ldc + cc) = v1;
            }
        }
    }
}

// ---------------------------------------------------------------------------
// K5: per-row epilogue
// ---------------------------------------------------------------------------
__global__ void final_kernel(const float* __restrict__ z,
                             const float* __restrict__ inv_mass,
                             const float* __restrict__ diffusion,
                             float* __restrict__ out)
{
    int row = blockIdx.x;
    int j   = threadIdx.x;

    float p1  = g_P1[(long)row * LD + j];
    float p2  = g_P2[(long)row * LD + j];
    float dif = diffusion[j];

    float sgn  = (dif > 0.f) ? 1.f : ((dif < 0.f) ? -1.f : 0.f);
    float sden = (fabsf(dif) > 1e-7f) ? dif : sgn * 1e-7f;
    float r    = (p1 - p2) / sden;
    float sq   = r * r;

    __shared__ float wsum[8];
    #pragma unroll
    for (int off = 16; off > 0; off >>= 1)
        sq += __shfl_down_sync(0xffffffffu, sq, off);
    if ((j & 31) == 0) wsum[j >> 5] = sq;
    __syncthreads();

    long dbase = (long)row * OUTC;
    long obase = (long)NB * OUTC + dbase;

    if (j == 0) {
        float s = 0.f;
        #pragma unroll
        for (int w = 0; w < 8; ++w) s += wsum[w];
        out[dbase + 512] = s;
        out[obase + 512] = 0.f;
    }
    float mom = z[(long)row * ZLD + 256 + j];
    out[dbase + j]       = inv_mass[j] * mom;
    out[dbase + 256 + j] = p2;
    out[obase + j]       = 0.f;
    out[obase + 256 + j] = dif;
}

// ---------------------------------------------------------------------------
extern "C" void kernel_launch(void* const* d_in, const int* in_sizes, int n_in,
                              void* d_out, int out_size)
{
    const float* z    = (const float*)d_in[0];
    const float* ts   = (const float*)d_in[1];
    const float* t    = (const float*)d_in[2];
    const float* ctx  = (const float*)d_in[3];
    const float* im   = (const float*)d_in[4];
    const float* dif  = (const float*)d_in[5];
    const float* Wc1  = (const float*)d_in[6];
    const float* bc1  = (const float*)d_in[7];
    const float* Wc2  = (const float*)d_in[8];
    const float* bc2  = (const float*)d_in[9];
    const float* Wh1  = (const float*)d_in[10];
    const float* bh1  = (const float*)d_in[11];
    const float* Wh2  = (const float*)d_in[12];
    const float* bh2  = (const float*)d_in[13];
    float* out = (float*)d_out;

    __half *pX, *pH1, *pH2;
    __half *pWh1, *pWc1, *pWh2, *pWc2;
    float *pP1, *pP2;
    cudaGetSymbolAddress((void**)&pX,  g_X);
    cudaGetSymbolAddress((void**)&pH1, g_H1);
    cudaGetSymbolAddress((void**)&pH2, g_H2);
    cudaGetSymbolAddress((void**)&pP1, g_P1);
    cudaGetSymbolAddress((void**)&pP2, g_P2);
    cudaGetSymbolAddress((void**)&pWh1, g_Wh1);
    cudaGetSymbolAddress((void**)&pWc1, g_Wc1);
    cudaGetSymbolAddress((void**)&pWh2, g_Wh2);
    cudaGetSymbolAddress((void**)&pWc2, g_Wc2);

    const int smem_bytes = NSTAGE * STAGE;   // 48 KB
    cudaFuncSetAttribute(mma_gemm2<1>, cudaFuncAttributeMaxDynamicSharedMemorySize, smem_bytes);
    cudaFuncSetAttribute(mma_gemm2<0>, cudaFuncAttributeMaxDynamicSharedMemorySize, smem_bytes);

    // weight prep: all 4 transpose jobs in one launch
    wtrans_all<<<dim3(32, 32, 4), dim3(32, 32)>>>(
        Wh1, Wc1, Wh2, Wc2, pWh1, pWc1, pWh2, pWc2);

    // X build (fp16)
    prep_kernel<<<(NB * XK) / 256, 256>>>(z, ctx, ts, t);

    // Layer 1 (batched): z=0 H1 = tanh(pm@Wh1+bh1) K=512 ; z=1 H2 = tanh(X@Wc1+bc1) K=1024
    mma_gemm2<1><<<dim3(HD / 128, NB / 128, 2), 256, smem_bytes>>>(
        pX, pWh1, bh1, pH1, nullptr, 512,
        pX, pWc1, bc1, pH2, nullptr, 1024,
        XK, HD);

    // Layer 2 (batched): z=0 P1 = H1@Wh2+bh2 ; z=1 P2 = H2@Wc2+bc2   (N=256)
    mma_gemm2<0><<<dim3(LD / 128, NB / 128, 2), 256, smem_bytes>>>(
        pH1, pWh2, bh2, nullptr, pP1, 1024,
        pH2, pWc2, bc2, nullptr, pP2, 1024,
        HD, LD);

    final_kernel<<<NB, 256>>>(z, im, dif, out);
}